// round 8
// baseline (speedup 1.0000x reference)
#include <cuda_runtime.h>
#include <cstdint>

#define B   8
#define C   512
#define K   19
#define HW  16384
#define INV_HW (1.0f / 16384.0f)

typedef unsigned long long u64;

// scratch (__device__ globals: allocation-free rule)
__device__ float g_cf[B * K * C];      // class_feat accumulator
__device__ float g_filt[B * K * C];    // dynamic filters
__device__ float g_mask[B * K * HW];   // sigmoid mask (~10 MB)

// ---- packed f32x2 helpers ----
__device__ __forceinline__ u64 pack2(float lo, float hi) {
    u64 r; asm("mov.b64 %0, {%1, %2};" : "=l"(r) : "f"(lo), "f"(hi)); return r;
}
__device__ __forceinline__ void fma2(u64& d, u64 a, u64 b) {
    asm("fma.rn.f32x2 %0, %1, %2, %0;" : "+l"(d) : "l"(a), "l"(b));
}
__device__ __forceinline__ float2 unpack2(u64 v) {
    float2 f; asm("mov.b64 {%0, %1}, %2;" : "=f"(f.x), "=f"(f.y) : "l"(v)); return f;
}
__device__ __forceinline__ float sigmoidf_(float z) {
    return 1.0f / (1.0f + __expf(-z));
}

// ---------------------------------------------------------------------------
// Kernel 0: zero class_feat accumulator
// ---------------------------------------------------------------------------
__global__ void zero_cf_kernel() {
    int i = blockIdx.x * blockDim.x + threadIdx.x;
    if (i < B * K * C) g_cf[i] = 0.0f;
}

// ---------------------------------------------------------------------------
// Kernel 1: mask = sigmoid(Wm @ x + bm) -> g_mask
//   block = 128 thr, thread = 2 adjacent px x 19 k, acc lanes = c-pairs
//   tile = 256 px, grid = (64, 8) = 512 blocks; smem 38912 B (4-5 blocks/SM)
//   per 2c: 2 LDG.64 + 2 packs + 19 natural LDS.64 + 38 FFMA2
// ---------------------------------------------------------------------------
#define MK_TPB 128
#define MK_T   256

__global__ __launch_bounds__(MK_TPB) void mask_kernel(
    const float* __restrict__ x,
    const float* __restrict__ Wm,
    const float* __restrict__ bm)
{
    __shared__ __align__(16) float sW[K * C];   // 38912 B

    const int tid = threadIdx.x;
    const int b   = blockIdx.y;
    const int p0  = blockIdx.x * MK_T;

    for (int i = tid; i < K * C / 4; i += MK_TPB)
        ((float4*)sW)[i] = ((const float4*)Wm)[i];
    __syncthreads();

    const int px = p0 + 2 * tid;
    const float* __restrict__ xc = x + (size_t)b * C * HW + px;

    u64 accA[K], accB[K];   // lanes = (c even, c odd) partial sums
#pragma unroll
    for (int k = 0; k < K; k++) { accA[k] = 0ULL; accB[k] = 0ULL; }

#pragma unroll 2
    for (int c = 0; c < C; c += 2) {
        float2 l0 = *(const float2*)(xc);        // (x[c,pxA], x[c,pxB])
        float2 l1 = *(const float2*)(xc + HW);   // (x[c+1,pxA], x[c+1,pxB])
        xc += 2 * HW;
        u64 xA = pack2(l0.x, l1.x);              // pxA: (c, c+1)
        u64 xB = pack2(l0.y, l1.y);              // pxB: (c, c+1)
#pragma unroll
        for (int k = 0; k < K; k++) {
            u64 w = *(const u64*)&sW[k * C + c]; // natural pair, LDS.64 bcast
            fma2(accA[k], w, xA);
            fma2(accB[k], w, xB);
        }
    }

#pragma unroll
    for (int k = 0; k < K; k++) {
        float bv = __ldg(&bm[k]);
        float2 a = unpack2(accA[k]);
        float2 c2 = unpack2(accB[k]);
        float2 m;
        m.x = sigmoidf_(a.x + a.y + bv);
        m.y = sigmoidf_(c2.x + c2.y + bv);
        *(float2*)&g_mask[((size_t)b * K + k) * HW + px] = m;
    }
}

// ---------------------------------------------------------------------------
// Kernel 2: pooling  g_cf[b,k,c] += sum_p mask[b,k,p] * x[b,c,p]
//   block = 128 thr, thread = 2 channels x 19 k, acc lanes = p-pairs
//   tile = 256 px, chgrp covers 256 channels; grid = (64, 2, 8) = 1024 blocks
//   per 4p: 2 LDG.128 + 19 LDS.128 + 76 FFMA2 (zero pack movs)
// ---------------------------------------------------------------------------
#define PL_TPB 128
#define PL_T   256

__global__ __launch_bounds__(PL_TPB) void pool_kernel(const float* __restrict__ x)
{
    __shared__ __align__(16) float sM[K * PL_T];   // 19456 B

    const int tid = threadIdx.x;
    const int b   = blockIdx.z;
    const int p0  = blockIdx.x * PL_T;

    {
        const float* mb = g_mask + (size_t)b * K * HW + p0;
        for (int i = tid; i < K * (PL_T / 4); i += PL_TPB) {
            int k = i / (PL_T / 4);
            int j = i - k * (PL_T / 4);
            ((float4*)sM)[i] = *(const float4*)(mb + (size_t)k * HW + j * 4);
        }
    }
    __syncthreads();

    const int ch0 = blockIdx.y * 256 + tid;       // channel 0
    const int ch1 = ch0 + 128;                    // channel 1
    const float* __restrict__ xp0 = x + (size_t)b * C * HW + (size_t)ch0 * HW + p0;
    const float* __restrict__ xp1 = x + (size_t)b * C * HW + (size_t)ch1 * HW + p0;

    u64 a0[K], a1[K];
#pragma unroll
    for (int k = 0; k < K; k++) { a0[k] = 0ULL; a1[k] = 0ULL; }

#pragma unroll 2
    for (int p = 0; p < PL_T; p += 4) {
        ulonglong2 v0 = *(const ulonglong2*)(xp0 + p);  // natural p-pairs
        ulonglong2 v1 = *(const ulonglong2*)(xp1 + p);
#pragma unroll
        for (int k = 0; k < K; k++) {
            ulonglong2 m = *(const ulonglong2*)&sM[k * PL_T + p];  // LDS.128 bcast
            fma2(a0[k], m.x, v0.x); fma2(a0[k], m.y, v0.y);
            fma2(a1[k], m.x, v1.x); fma2(a1[k], m.y, v1.y);
        }
    }

#pragma unroll
    for (int k = 0; k < K; k++) {
        float2 s = unpack2(a0[k]);
        atomicAdd(&g_cf[((size_t)b * K + k) * C + ch0], s.x + s.y);
        float2 t = unpack2(a1[k]);
        atomicAdd(&g_cf[((size_t)b * K + k) * C + ch1], t.x + t.y);
    }
}

// ---------------------------------------------------------------------------
// Kernel 3: filters[b,k,o] = sum_c Wf[k,o,c] * cf[b,k,c]/HW + bf[k,o]
//   warp-per-output: grid (K, 64), block 256 (8 warps = 8 outputs)
//   Wf read exactly once, coalesced float4; 9728 warps total
// ---------------------------------------------------------------------------
__global__ __launch_bounds__(256) void filters_kernel(
    const float* __restrict__ Wf,
    const float* __restrict__ bf)
{
    __shared__ __align__(16) float scf[B * C];   // 16 KB

    const int k    = blockIdx.x;
    const int tid  = threadIdx.x;
    const int warp = tid >> 5;
    const int lane = tid & 31;

    for (int i = tid; i < B * C; i += 256) {
        int bb = i >> 9, cc = i & 511;
        scf[i] = g_cf[((size_t)bb * K + k) * C + cc] * INV_HW;
    }
    __syncthreads();

    const int o = blockIdx.y * 8 + warp;
    const float4* __restrict__ wrow4 = (const float4*)(Wf + ((size_t)k * C + o) * C);
    const float4* __restrict__ scf4  = (const float4*)scf;

    float acc[B];
#pragma unroll
    for (int bb = 0; bb < B; bb++) acc[bb] = 0.0f;

#pragma unroll
    for (int i = 0; i < 4; i++) {
        float4 w = wrow4[i * 32 + lane];          // coalesced 512B per instr
#pragma unroll
        for (int bb = 0; bb < B; bb++) {
            float4 f = scf4[bb * 128 + i * 32 + lane];
            acc[bb] += w.x * f.x + w.y * f.y + w.z * f.z + w.w * f.w;
        }
    }

#pragma unroll
    for (int bb = 0; bb < B; bb++) {
#pragma unroll
        for (int s = 16; s > 0; s >>= 1)
            acc[bb] += __shfl_xor_sync(0xffffffffu, acc[bb], s);
    }

    if (lane == 0) {
        float bias = __ldg(&bf[k * C + o]);
#pragma unroll
        for (int bb = 0; bb < B; bb++)
            g_filt[((size_t)bb * K + k) * C + o] = acc[bb] + bias;
    }
}

// ---------------------------------------------------------------------------
// Kernel 4: pred[b,k,p] = sum_c filters[b,k,c] * x[b,c,p]
//   identical structure to mask_kernel (no sigmoid), writes d_out
// ---------------------------------------------------------------------------
__global__ __launch_bounds__(MK_TPB) void pred_kernel(
    const float* __restrict__ x,
    float* __restrict__ out)
{
    __shared__ __align__(16) float sF[K * C];

    const int tid = threadIdx.x;
    const int b   = blockIdx.y;
    const int p0  = blockIdx.x * MK_T;

    {
        const float4* fb = (const float4*)(g_filt + (size_t)b * K * C);
        for (int i = tid; i < K * C / 4; i += MK_TPB)
            ((float4*)sF)[i] = fb[i];
    }
    __syncthreads();

    const int px = p0 + 2 * tid;
    const float* __restrict__ xc = x + (size_t)b * C * HW + px;

    u64 accA[K], accB[K];
#pragma unroll
    for (int k = 0; k < K; k++) { accA[k] = 0ULL; accB[k] = 0ULL; }

#pragma unroll 2
    for (int c = 0; c < C; c += 2) {
        float2 l0 = *(const float2*)(xc);
        float2 l1 = *(const float2*)(xc + HW);
        xc += 2 * HW;
        u64 xA = pack2(l0.x, l1.x);
        u64 xB = pack2(l0.y, l1.y);
#pragma unroll
        for (int k = 0; k < K; k++) {
            u64 w = *(const u64*)&sF[k * C + c];
            fma2(accA[k], w, xA);
            fma2(accB[k], w, xB);
        }
    }

#pragma unroll
    for (int k = 0; k < K; k++) {
        float2 a = unpack2(accA[k]);
        float2 c2 = unpack2(accB[k]);
        float2 o = make_float2(a.x + a.y, c2.x + c2.y);
        *(float2*)&out[((size_t)b * K + k) * HW + px] = o;
    }
}

// ---------------------------------------------------------------------------
extern "C" void kernel_launch(void* const* d_in, const int* in_sizes, int n_in,
                              void* d_out, int out_size)
{
    const float* x  = (const float*)d_in[0];
    const float* Wm = (const float*)d_in[1];
    const float* bm = (const float*)d_in[2];
    const float* Wf = (const float*)d_in[3];
    const float* bf = (const float*)d_in[4];
    float* out = (float*)d_out;

    zero_cf_kernel<<<(B * K * C + 255) / 256, 256>>>();
    mask_kernel<<<dim3(HW / MK_T, B), MK_TPB>>>(x, Wm, bm);
    pool_kernel<<<dim3(HW / PL_T, 2, B), PL_TPB>>>(x);
    filters_kernel<<<dim3(K, C / 8), 256>>>(Wf, bf);
    pred_kernel<<<dim3(HW / MK_T, B), MK_TPB>>>(x, out);
}

// round 10
// speedup vs baseline: 2.0319x; 2.0319x over previous
#include <cuda_runtime.h>
#include <cstdint>

#define B   8
#define C   512
#define K   19
#define HW  16384
#define INV_HW (1.0f / 16384.0f)

// scratch (__device__ globals: allocation-free rule)
__device__ float g_cf[B * K * C];      // class_feat accumulator
__device__ float g_filt[B * K * C];    // dynamic filters
__device__ float g_mask[B * K * HW];   // sigmoid mask (~10 MB)

__device__ __forceinline__ float sigmoidf_(float z) {
    return 1.0f / (1.0f + __expf(-z));
}

// ---------------------------------------------------------------------------
// Kernel 0: zero class_feat accumulator
// ---------------------------------------------------------------------------
__global__ void zero_cf_kernel() {
    int i = blockIdx.x * blockDim.x + threadIdx.x;
    if (i < B * K * C) g_cf[i] = 0.0f;
}

// ---------------------------------------------------------------------------
// Kernel 1: mask = sigmoid(Wm @ x + bm) -> g_mask      (scalar FFMA)
//   TPB=128, thread = 2 adjacent px x 19 k (38 fp32 accs)
//   tile = 256 px, grid = (64, 8) = 512 blocks, smem 38912 B
//   per 4c: 4 LDG.64 + 19 LDS.128 + 152 FFMA  (fma share ~82%)
// ---------------------------------------------------------------------------
#define MK_TPB 128
#define MK_T   256

__global__ __launch_bounds__(MK_TPB) void mask_kernel(
    const float* __restrict__ x,
    const float* __restrict__ Wm,
    const float* __restrict__ bm)
{
    __shared__ __align__(16) float sW[K * C];   // 38912 B

    const int tid = threadIdx.x;
    const int b   = blockIdx.y;
    const int p0  = blockIdx.x * MK_T;

    for (int i = tid; i < K * C / 4; i += MK_TPB)
        ((float4*)sW)[i] = ((const float4*)Wm)[i];
    __syncthreads();

    const int px = p0 + 2 * tid;
    const float* __restrict__ xc = x + (size_t)b * C * HW + px;

    float accA[K], accB[K];
#pragma unroll
    for (int k = 0; k < K; k++) { accA[k] = 0.0f; accB[k] = 0.0f; }

#pragma unroll 2
    for (int c = 0; c < C; c += 4) {
        float2 l0 = *(const float2*)(xc);            // ch c  : (pxA, pxB)
        float2 l1 = *(const float2*)(xc + HW);       // ch c+1
        float2 l2 = *(const float2*)(xc + 2 * HW);   // ch c+2
        float2 l3 = *(const float2*)(xc + 3 * HW);   // ch c+3
        xc += 4 * HW;
#pragma unroll
        for (int k = 0; k < K; k++) {
            float4 w = *(const float4*)&sW[k * C + c];   // LDS.128 bcast
            accA[k] += w.x * l0.x + w.y * l1.x + w.z * l2.x + w.w * l3.x;
            accB[k] += w.x * l0.y + w.y * l1.y + w.z * l2.y + w.w * l3.y;
        }
    }

#pragma unroll
    for (int k = 0; k < K; k++) {
        float bv = __ldg(&bm[k]);
        float2 m;
        m.x = sigmoidf_(accA[k] + bv);
        m.y = sigmoidf_(accB[k] + bv);
        *(float2*)&g_mask[((size_t)b * K + k) * HW + px] = m;
    }
}

// ---------------------------------------------------------------------------
// Kernel 2: pooling  g_cf[b,k,c] += sum_p mask[b,k,p] * x[b,c,p]  (scalar)
//   TPB=128, thread = 2 channels x 19 k (38 fp32 accs)
//   tile = 256 px, grid = (64, 2, 8) = 1024 blocks, smem 19456 B
//   per 4p: 2 LDG.128 + 19 LDS.128 + 152 FFMA  (fma share ~88%)
// ---------------------------------------------------------------------------
#define PL_TPB 128
#define PL_T   256

__global__ __launch_bounds__(PL_TPB) void pool_kernel(const float* __restrict__ x)
{
    __shared__ __align__(16) float sM[K * PL_T];   // 19456 B

    const int tid = threadIdx.x;
    const int b   = blockIdx.z;
    const int p0  = blockIdx.x * PL_T;

    {
        const float* mb = g_mask + (size_t)b * K * HW + p0;
        for (int i = tid; i < K * (PL_T / 4); i += PL_TPB) {
            int k = i / (PL_T / 4);
            int j = i - k * (PL_T / 4);
            ((float4*)sM)[i] = *(const float4*)(mb + (size_t)k * HW + j * 4);
        }
    }
    __syncthreads();

    const int ch0 = blockIdx.y * 256 + tid;
    const int ch1 = ch0 + 128;
    const float* __restrict__ xp0 = x + (size_t)b * C * HW + (size_t)ch0 * HW + p0;
    const float* __restrict__ xp1 = x + (size_t)b * C * HW + (size_t)ch1 * HW + p0;

    float a0[K], a1[K];
#pragma unroll
    for (int k = 0; k < K; k++) { a0[k] = 0.0f; a1[k] = 0.0f; }

#pragma unroll 2
    for (int p = 0; p < PL_T; p += 4) {
        float4 v0 = *(const float4*)(xp0 + p);
        float4 v1 = *(const float4*)(xp1 + p);
#pragma unroll
        for (int k = 0; k < K; k++) {
            float4 m = *(const float4*)&sM[k * PL_T + p];   // LDS.128 bcast
            a0[k] += m.x * v0.x + m.y * v0.y + m.z * v0.z + m.w * v0.w;
            a1[k] += m.x * v1.x + m.y * v1.y + m.z * v1.z + m.w * v1.w;
        }
    }

#pragma unroll
    for (int k = 0; k < K; k++) {
        atomicAdd(&g_cf[((size_t)b * K + k) * C + ch0], a0[k]);
        atomicAdd(&g_cf[((size_t)b * K + k) * C + ch1], a1[k]);
    }
}

// ---------------------------------------------------------------------------
// Kernel 3: filters[b,k,o] = sum_c Wf[k,o,c] * cf[b,k,c]/HW + bf[k,o]
//   warp-per-output, Wf read once coalesced (R8-proven: 21 us)
// ---------------------------------------------------------------------------
__global__ __launch_bounds__(256) void filters_kernel(
    const float* __restrict__ Wf,
    const float* __restrict__ bf)
{
    __shared__ __align__(16) float scf[B * C];   // 16 KB

    const int k    = blockIdx.x;
    const int tid  = threadIdx.x;
    const int warp = tid >> 5;
    const int lane = tid & 31;

    for (int i = tid; i < B * C; i += 256) {
        int bb = i >> 9, cc = i & 511;
        scf[i] = g_cf[((size_t)bb * K + k) * C + cc] * INV_HW;
    }
    __syncthreads();

    const int o = blockIdx.y * 8 + warp;
    const float4* __restrict__ wrow4 = (const float4*)(Wf + ((size_t)k * C + o) * C);
    const float4* __restrict__ scf4  = (const float4*)scf;

    float acc[B];
#pragma unroll
    for (int bb = 0; bb < B; bb++) acc[bb] = 0.0f;

#pragma unroll
    for (int i = 0; i < 4; i++) {
        float4 w = wrow4[i * 32 + lane];
#pragma unroll
        for (int bb = 0; bb < B; bb++) {
            float4 f = scf4[bb * 128 + i * 32 + lane];
            acc[bb] += w.x * f.x + w.y * f.y + w.z * f.z + w.w * f.w;
        }
    }

#pragma unroll
    for (int bb = 0; bb < B; bb++) {
#pragma unroll
        for (int s = 16; s > 0; s >>= 1)
            acc[bb] += __shfl_xor_sync(0xffffffffu, acc[bb], s);
    }

    if (lane == 0) {
        float bias = __ldg(&bf[k * C + o]);
#pragma unroll
        for (int bb = 0; bb < B; bb++)
            g_filt[((size_t)bb * K + k) * C + o] = acc[bb] + bias;
    }
}

// ---------------------------------------------------------------------------
// Kernel 4: pred[b,k,p] = sum_c filters[b,k,c] * x[b,c,p]   (scalar FFMA)
//   identical structure to mask_kernel, writes d_out
// ---------------------------------------------------------------------------
__global__ __launch_bounds__(MK_TPB) void pred_kernel(
    const float* __restrict__ x,
    float* __restrict__ out)
{
    __shared__ __align__(16) float sF[K * C];

    const int tid = threadIdx.x;
    const int b   = blockIdx.y;
    const int p0  = blockIdx.x * MK_T;

    {
        const float4* fb = (const float4*)(g_filt + (size_t)b * K * C);
        for (int i = tid; i < K * C / 4; i += MK_TPB)
            ((float4*)sF)[i] = fb[i];
    }
    __syncthreads();

    const int px = p0 + 2 * tid;
    const float* __restrict__ xc = x + (size_t)b * C * HW + px;

    float accA[K], accB[K];
#pragma unroll
    for (int k = 0; k < K; k++) { accA[k] = 0.0f; accB[k] = 0.0f; }

#pragma unroll 2
    for (int c = 0; c < C; c += 4) {
        float2 l0 = *(const float2*)(xc);
        float2 l1 = *(const float2*)(xc + HW);
        float2 l2 = *(const float2*)(xc + 2 * HW);
        float2 l3 = *(const float2*)(xc + 3 * HW);
        xc += 4 * HW;
#pragma unroll
        for (int k = 0; k < K; k++) {
            float4 w = *(const float4*)&sF[k * C + c];
            accA[k] += w.x * l0.x + w.y * l1.x + w.z * l2.x + w.w * l3.x;
            accB[k] += w.x * l0.y + w.y * l1.y + w.z * l2.y + w.w * l3.y;
        }
    }

#pragma unroll
    for (int k = 0; k < K; k++) {
        float2 o = make_float2(accA[k], accB[k]);
        *(float2*)&out[((size_t)b * K + k) * HW + px] = o;
    }
}

// ---------------------------------------------------------------------------
extern "C" void kernel_launch(void* const* d_in, const int* in_sizes, int n_in,
                              void* d_out, int out_size)
{
    const float* x  = (const float*)d_in[0];
    const float* Wm = (const float*)d_in[1];
    const float* bm = (const float*)d_in[2];
    const float* Wf = (const float*)d_in[3];
    const float* bf = (const float*)d_in[4];
    float* out = (float*)d_out;

    zero_cf_kernel<<<(B * K * C + 255) / 256, 256>>>();
    mask_kernel<<<dim3(HW / MK_T, B), MK_TPB>>>(x, Wm, bm);
    pool_kernel<<<dim3(HW / PL_T, 2, B), PL_TPB>>>(x);
    filters_kernel<<<dim3(K, C / 8), 256>>>(Wf, bf);
    pred_kernel<<<dim3(HW / MK_T, B), MK_TPB>>>(x, out);
}